// round 1
// baseline (speedup 1.0000x reference)
#include <cuda_runtime.h>

#define NIMG 4
#define HW (1024*1024)
#define PBINS 10
#define LBINS 6
#define NBINS 66              // 60 inter bins (l*10+p) + 6 label-count bins (60+l)
#define TPB 128
#define BLOCKS_PER_IMG 128
#define VECS_PER_IMG (HW/4)   // 262144 float4 per image
#define VECS_PER_BLOCK (VECS_PER_IMG/BLOCKS_PER_IMG)  // 2048
#define ITERS (VECS_PER_BLOCK/TPB)                    // 16

// Global scratch (no cudaMalloc allowed): per-image bins.
__device__ float g_bins[NIMG][NBINS];

__global__ void sc_zero_kernel() {
    int i = threadIdx.x;
    if (i < NIMG * NBINS) ((float*)g_bins)[i] = 0.0f;
}

__global__ void __launch_bounds__(TPB)
sc_accum_kernel(const float* __restrict__ pred,
                const int* __restrict__ pconn,
                const int* __restrict__ lconn) {
    // Per-thread private histogram columns: s[bin][tid].
    // Address stride across bins is 128 floats (=512B, multiple of 128B),
    // so bank = tid%32 -> conflict-free regardless of bin value. No atomics.
    __shared__ float s[NBINS][TPB];
    __shared__ float s_part[NBINS][TPB / 32];

    const int tid = threadIdx.x;
    const int img = blockIdx.y;

    #pragma unroll
    for (int b = 0; b < NBINS; b++) s[b][tid] = 0.0f;
    __syncthreads();

    const size_t base = (size_t)img * VECS_PER_IMG;
    const float4* __restrict__ p4  = ((const float4*)pred)  + base;
    const int4*   __restrict__ pc4 = ((const int4*)pconn)   + base;
    const int4*   __restrict__ lc4 = ((const int4*)lconn)   + base;

    int v = blockIdx.x * VECS_PER_BLOCK + tid;

    #pragma unroll 4
    for (int it = 0; it < ITERS; it++, v += TPB) {
        float4 p  = p4[v];
        int4   pc = pc4[v];
        int4   lc = lc4[v];

        s[lc.x * PBINS + pc.x][tid] += p.x;
        s[lc.y * PBINS + pc.y][tid] += p.y;
        s[lc.z * PBINS + pc.z][tid] += p.z;
        s[lc.w * PBINS + pc.w][tid] += p.w;
        s[60 + lc.x][tid] += 1.0f;
        s[60 + lc.y][tid] += 1.0f;
        s[60 + lc.z][tid] += 1.0f;
        s[60 + lc.w][tid] += 1.0f;
    }
    __syncthreads();

    // Reduce the 128 private columns per bin: warp shuffle, then 4 partials.
    const int lane = tid & 31;
    const int wid  = tid >> 5;
    #pragma unroll
    for (int b = 0; b < NBINS; b++) {
        float x = s[b][tid];                 // bank = tid%32, conflict-free
        x += __shfl_down_sync(0xFFFFFFFFu, x, 16);
        x += __shfl_down_sync(0xFFFFFFFFu, x, 8);
        x += __shfl_down_sync(0xFFFFFFFFu, x, 4);
        x += __shfl_down_sync(0xFFFFFFFFu, x, 2);
        x += __shfl_down_sync(0xFFFFFFFFu, x, 1);
        if (lane == 0) s_part[b][wid] = x;
    }
    __syncthreads();

    if (tid < NBINS) {
        float t = s_part[tid][0] + s_part[tid][1] + s_part[tid][2] + s_part[tid][3];
        atomicAdd(&g_bins[img][tid], t);
    }
}

__global__ void sc_finalize_kernel(float* __restrict__ out) {
    __shared__ float losses[NIMG];
    int i = threadIdx.x;
    if (i < NIMG) {
        const float* b = g_bins[i];

        // pred_area[p] = sum over all labels l of inter[l][p]
        float pa[PBINS];
        #pragma unroll
        for (int p = 0; p < PBINS; p++) {
            float sum = 0.0f;
            #pragma unroll
            for (int l = 0; l < LBINS; l++) sum += b[l * PBINS + p];
            pa[p] = sum;
        }

        // iou(l,p) for l>=1, p>=1:
        //   inter == 0 -> 0
        //   inter >  0 -> union = cnt[l] + pa[p] - inter > 0, iou = inter/union
        bool colnz[PBINS];
        #pragma unroll
        for (int p = 0; p < PBINS; p++) colnz[p] = false;

        float pair_conn_sum = 0.0f;
        #pragma unroll
        for (int l = 1; l < LBINS; l++) {
            float la = b[60 + l];
            float pc = 0.0f;
            int   pn = 0;
            #pragma unroll
            for (int p = 1; p < PBINS; p++) {
                float in = b[l * PBINS + p];
                if (in != 0.0f) {
                    float uni = la + pa[p] - in;
                    pc += in / uni;
                    pn++;
                    colnz[p] = true;
                }
            }
            if (pn > 0) pair_conn_sum += pc / (float)pn;
        }

        int lone = 0;
        #pragma unroll
        for (int p = 1; p < PBINS; p++) if (!colnz[p]) lone++;

        float denom = (float)(LBINS - 1) + (float)lone;
        losses[i] = 1.0f - pair_conn_sum / denom;
    }
    __syncthreads();
    if (i == 0)
        out[0] = (losses[0] + losses[1] + losses[2] + losses[3]) * 0.25f;
}

extern "C" void kernel_launch(void* const* d_in, const int* in_sizes, int n_in,
                              void* d_out, int out_size) {
    const float* pred  = (const float*)d_in[0];
    const int*   pconn = (const int*)d_in[1];
    const int*   lconn = (const int*)d_in[2];
    float* out = (float*)d_out;

    sc_zero_kernel<<<1, 512>>>();
    dim3 grid(BLOCKS_PER_IMG, NIMG);
    sc_accum_kernel<<<grid, TPB>>>(pred, pconn, lconn);
    sc_finalize_kernel<<<1, 32>>>(out);
}

// round 2
// speedup vs baseline: 1.0166x; 1.0166x over previous
#include <cuda_runtime.h>

#define NIMG 4
#define HW (1024*1024)
#define PBINS 10
#define LBINS 6
#define NBINS 66              // 60 inter bins (l*10+p) + 6 label-count bins (60+l)
#define TPB 128
#define BLOCKS_PER_IMG 128
#define TOTAL_BLOCKS (BLOCKS_PER_IMG * NIMG)
#define VECS_PER_IMG (HW/4)   // 262144 float4 per image
#define VECS_PER_BLOCK (VECS_PER_IMG/BLOCKS_PER_IMG)  // 2048
#define ITERS (VECS_PER_BLOCK/TPB)                    // 16

// Global scratch (zero-initialized at module load; kernel restores zeros
// before exit so every graph replay sees the same state).
__device__ float g_bins[NIMG][NBINS];
__device__ unsigned int g_ticket;

__global__ void __launch_bounds__(TPB)
sc_fused_kernel(const float* __restrict__ pred,
                const int* __restrict__ pconn,
                const int* __restrict__ lconn,
                float* __restrict__ out) {
    // Per-thread private histogram columns: s[bin][tid].
    // Row stride = 128 floats = 512B (multiple of 128B), so bank = tid%32
    // -> conflict-free regardless of bin value. No atomics in the hot loop.
    __shared__ float s[NBINS][TPB];
    __shared__ float s_part[NBINS][TPB / 32];
    __shared__ bool  s_last;

    const int tid = threadIdx.x;
    const int img = blockIdx.y;

    #pragma unroll
    for (int b = 0; b < NBINS; b++) s[b][tid] = 0.0f;
    __syncthreads();

    const size_t base = (size_t)img * VECS_PER_IMG;
    const float4* __restrict__ p4  = ((const float4*)pred)  + base;
    const int4*   __restrict__ pc4 = ((const int4*)pconn)   + base;
    const int4*   __restrict__ lc4 = ((const int4*)lconn)   + base;

    int v = blockIdx.x * VECS_PER_BLOCK + tid;

    #pragma unroll 4
    for (int it = 0; it < ITERS; it++, v += TPB) {
        float4 p  = p4[v];
        int4   pc = pc4[v];
        int4   lc = lc4[v];

        s[lc.x * PBINS + pc.x][tid] += p.x;
        s[lc.y * PBINS + pc.y][tid] += p.y;
        s[lc.z * PBINS + pc.z][tid] += p.z;
        s[lc.w * PBINS + pc.w][tid] += p.w;
        s[60 + lc.x][tid] += 1.0f;
        s[60 + lc.y][tid] += 1.0f;
        s[60 + lc.z][tid] += 1.0f;
        s[60 + lc.w][tid] += 1.0f;
    }
    __syncthreads();

    // Reduce 128 private columns per bin: warp shuffle, then 4 partials.
    const int lane = tid & 31;
    const int wid  = tid >> 5;
    #pragma unroll
    for (int b = 0; b < NBINS; b++) {
        float x = s[b][tid];                 // bank = tid%32, conflict-free
        x += __shfl_down_sync(0xFFFFFFFFu, x, 16);
        x += __shfl_down_sync(0xFFFFFFFFu, x, 8);
        x += __shfl_down_sync(0xFFFFFFFFu, x, 4);
        x += __shfl_down_sync(0xFFFFFFFFu, x, 2);
        x += __shfl_down_sync(0xFFFFFFFFu, x, 1);
        if (lane == 0) s_part[b][wid] = x;
    }
    __syncthreads();

    if (tid < NBINS) {
        float t = s_part[tid][0] + s_part[tid][1] + s_part[tid][2] + s_part[tid][3];
        atomicAdd(&g_bins[img][tid], t);
    }

    // ---- last-block-done: finalize inline, then restore scratch to zero ----
    if (tid == 0) {
        __threadfence();
        unsigned int t = atomicAdd(&g_ticket, 1u);
        s_last = (t == TOTAL_BLOCKS - 1);
    }
    __syncthreads();
    if (!s_last) return;

    // All 512 blocks' atomics are visible (threadfence-before-ticket).
    // Read bins with .cg (L2) to avoid any stale L1 lines.
    __shared__ float losses[NIMG];
    __shared__ float binc[NIMG][NBINS];

    if (tid < NIMG * NBINS)
        ((float*)binc)[tid] = __ldcg(&((const float*)g_bins)[tid]);
    if (tid >= 128 - (NIMG * NBINS - 128) && tid < 128) {
        int k = tid + (NIMG * NBINS - 128) - (NIMG * NBINS - 128); // no-op guard
    }
    // NIMG*NBINS = 264 > TPB: second chunk
    {
        int k = tid + TPB;
        if (k < NIMG * NBINS)
            ((float*)binc)[k] = __ldcg(&((const float*)g_bins)[k]);
        k = tid + 2 * TPB;
        if (k < NIMG * NBINS)
            ((float*)binc)[k] = __ldcg(&((const float*)g_bins)[k]);
    }
    __syncthreads();

    if (tid < NIMG) {
        const float* b = binc[tid];

        // pred_area[p] = sum_l inter[l][p]
        float pa[PBINS];
        #pragma unroll
        for (int p = 0; p < PBINS; p++) {
            float sum = 0.0f;
            #pragma unroll
            for (int l = 0; l < LBINS; l++) sum += b[l * PBINS + p];
            pa[p] = sum;
        }

        bool colnz[PBINS];
        #pragma unroll
        for (int p = 0; p < PBINS; p++) colnz[p] = false;

        float pair_conn_sum = 0.0f;
        #pragma unroll
        for (int l = 1; l < LBINS; l++) {
            float la = b[60 + l];
            float pc = 0.0f;
            int   pn = 0;
            #pragma unroll
            for (int p = 1; p < PBINS; p++) {
                float in = b[l * PBINS + p];
                if (in != 0.0f) {
                    float uni = la + pa[p] - in;
                    pc += in / uni;
                    pn++;
                    colnz[p] = true;
                }
            }
            if (pn > 0) pair_conn_sum += pc / (float)pn;
        }

        int lone = 0;
        #pragma unroll
        for (int p = 1; p < PBINS; p++) if (!colnz[p]) lone++;

        float denom = (float)(LBINS - 1) + (float)lone;
        losses[tid] = 1.0f - pair_conn_sum / denom;
    }
    __syncthreads();

    if (tid == 0)
        out[0] = (losses[0] + losses[1] + losses[2] + losses[3]) * 0.25f;

    // Restore scratch to zero for the next (graph-replayed) call.
    {
        int k = tid;
        #pragma unroll
        for (int c = 0; c < 3; c++, k += TPB)
            if (k < NIMG * NBINS) ((float*)g_bins)[k] = 0.0f;
    }
    if (tid == 0) g_ticket = 0u;
}

extern "C" void kernel_launch(void* const* d_in, const int* in_sizes, int n_in,
                              void* d_out, int out_size) {
    const float* pred  = (const float*)d_in[0];
    const int*   pconn = (const int*)d_in[1];
    const int*   lconn = (const int*)d_in[2];
    float* out = (float*)d_out;

    dim3 grid(BLOCKS_PER_IMG, NIMG);
    sc_fused_kernel<<<grid, TPB>>>(pred, pconn, lconn, out);
}